// round 1
// baseline (speedup 1.0000x reference)
#include <cuda_runtime.h>

// Problem constants
// B=8, N=64, T=128, E=128, H=8, R=4, DH=16
// groups = B*N*T = 65536; rows = groups*R = 262144

#define NGROUPS 65536
#define NROWS   262144

// ---------------- scratch (device globals; no allocation allowed) ----------
__device__ float g_WqkvT[128 * 384];            // [k][c] folded qkv weight (c: 0-127 q, 128-255 k, 256-383 v)
__device__ float g_bqkv[384];                   // folded qkv bias
__device__ float g_WofT[512 * 128];             // [c][eo] folded output weight
__device__ float g_bof[128];                    // folded output bias
__device__ float g_qkv[(size_t)NROWS * 384];    // per-row q|k|v
__device__ float g_ocat[(size_t)NGROUPS * 512]; // attention output (pre out_w), [g][r*128 + h*16 + d]

// ---------------- weight folding ----------------
// rows 0..383  : qkv fold.  row = sub*128 + f  (sub: 0=q,1=k,2=v)
//    Wqkvf[f][k] = sum_e in_w[(sub*128+f)*128+e] * W{q,k,v}[e*128+k]
//    stored transposed: g_WqkvT[k*384 + row]
//    g_bqkv[row] = sum_e in_w[row*128+e]*b{q,k,v}[e] + in_b[row]
// rows 384..895: output fold. idx = row-384, r = idx/128, eo = idx%128
//    Wbig[eo][r*128+e] = sum_f fc_w[eo*512 + r*128 + f] * out_w[f*128+e]
//    stored transposed: g_WofT[(r*128+e)*128 + eo]
//    g_bof[eo] = fc_b[eo] + sum_c fc_w[eo*512+c]*out_b[c&127]
__global__ void prep_kernel(const float* __restrict__ Wq, const float* __restrict__ bq,
                            const float* __restrict__ Wk, const float* __restrict__ bk,
                            const float* __restrict__ Wv, const float* __restrict__ bv,
                            const float* __restrict__ in_w, const float* __restrict__ in_b,
                            const float* __restrict__ out_w, const float* __restrict__ out_b,
                            const float* __restrict__ fc_w, const float* __restrict__ fc_b)
{
    int row = blockIdx.x;   // 0..895
    int t   = threadIdx.x;  // 0..127

    if (row < 384) {
        int sub = row >> 7;
        const float* W    = (sub == 0) ? Wq : (sub == 1) ? Wk : Wv;
        const float* bvec = (sub == 0) ? bq : (sub == 1) ? bk : bv;
        const float* iw   = in_w + (size_t)row * 128;
        float acc = 0.f;
        #pragma unroll 4
        for (int e = 0; e < 128; e++)
            acc = fmaf(iw[e], W[e * 128 + t], acc);
        g_WqkvT[t * 384 + row] = acc;
        if (t == 0) {
            float b = in_b[row];
            for (int e = 0; e < 128; e++) b = fmaf(iw[e], bvec[e], b);
            g_bqkv[row] = b;
        }
    } else {
        int idx = row - 384;
        int r  = idx >> 7;
        int eo = idx & 127;
        const float* fw = fc_w + (size_t)eo * 512 + r * 128;
        float acc = 0.f;
        #pragma unroll 4
        for (int f = 0; f < 128; f++)
            acc = fmaf(fw[f], out_w[f * 128 + t], acc);
        g_WofT[(r * 128 + t) * 128 + eo] = acc;
        if (t == 0 && r == 0) {
            float b = fc_b[eo];
            const float* fwa = fc_w + (size_t)eo * 512;
            for (int c = 0; c < 512; c++) b = fmaf(fwa[c], out_b[c & 127], b);
            g_bof[eo] = b;
        }
    }
}

// ---------------- GEMM1: X[32,128] @ WqkvT -> qkv[32,384] per block ----------
// block = 256 threads, 8 groups (32 rows). Thread (tm=t/64, tn=t%64):
// rows tm*8+i (i<8), cols tn + j*64 (j<6) -> 48 accumulators.
__global__ void __launch_bounds__(256) qkv_gemm(const float* __restrict__ node,
                                                const float* __restrict__ sub)
{
    __shared__ float Xs[32 * 128];
    int t  = threadIdx.x;
    int g0 = blockIdx.x * 8;

    // gather X: row m = local_g*4 + r;  r==0 -> node row, else subgraph (strided by 3)
    for (int idx = t; idx < 4096; idx += 256) {
        int m = idx >> 7, e = idx & 127;
        int g = g0 + (m >> 2), r = m & 3;
        Xs[idx] = (r == 0) ? node[(size_t)g * 128 + e]
                           : sub[(size_t)g * 384 + e * 3 + (r - 1)];
    }
    __syncthreads();

    int tm = t >> 6;   // 0..3
    int tn = t & 63;   // 0..63

    float acc[8][6];
    #pragma unroll
    for (int i = 0; i < 8; i++)
        #pragma unroll
        for (int j = 0; j < 6; j++) acc[i][j] = 0.f;

    const float* Wp = g_WqkvT + tn;
    #pragma unroll 4
    for (int k = 0; k < 128; k++) {
        float w[6];
        #pragma unroll
        for (int j = 0; j < 6; j++) w[j] = Wp[k * 384 + j * 64];
        #pragma unroll
        for (int i = 0; i < 8; i++) {
            float x = Xs[(tm * 8 + i) * 128 + k];
            #pragma unroll
            for (int j = 0; j < 6; j++) acc[i][j] = fmaf(x, w[j], acc[i][j]);
        }
    }

    #pragma unroll
    for (int i = 0; i < 8; i++) {
        size_t rowbase = (size_t)(g0 * 4 + tm * 8 + i) * 384;
        #pragma unroll
        for (int j = 0; j < 6; j++) {
            int c = tn + j * 64;
            g_qkv[rowbase + c] = acc[i][j] + g_bqkv[c];
        }
    }
}

// ---------------- attention: one thread per (group, head) -------------------
__global__ void __launch_bounds__(256) attn_kernel()
{
    int tid = blockIdx.x * 256 + threadIdx.x;
    int g = tid >> 3;
    int h = tid & 7;

    const float4* base = (const float4*)(g_qkv + (size_t)g * 1536 + h * 16);
    // in float4 units: row stride 96, k at +32, v at +64

    float4 q[4][4], kk[4][4];
    #pragma unroll
    for (int r = 0; r < 4; r++)
        #pragma unroll
        for (int d = 0; d < 4; d++) {
            q[r][d]  = base[r * 96 + d];
            kk[r][d] = base[r * 96 + 32 + d];
        }

    float s[4][4];
    #pragma unroll
    for (int r = 0; r < 4; r++)
        #pragma unroll
        for (int c = 0; c < 4; c++) {
            float a = 0.f;
            #pragma unroll
            for (int d = 0; d < 4; d++) {
                a = fmaf(q[r][d].x, kk[c][d].x, a);
                a = fmaf(q[r][d].y, kk[c][d].y, a);
                a = fmaf(q[r][d].z, kk[c][d].z, a);
                a = fmaf(q[r][d].w, kk[c][d].w, a);
            }
            s[r][c] = a * 0.25f;   // 1/sqrt(DH)
        }

    float attn[4][4];
    #pragma unroll
    for (int r = 0; r < 4; r++) {
        float m  = fmaxf(fmaxf(s[r][0], s[r][1]), fmaxf(s[r][2], s[r][3]));
        float e0 = __expf(s[r][0] - m), e1 = __expf(s[r][1] - m);
        float e2 = __expf(s[r][2] - m), e3 = __expf(s[r][3] - m);
        float inv = 1.f / (e0 + e1 + e2 + e3);
        attn[r][0] = e0 * inv; attn[r][1] = e1 * inv;
        attn[r][2] = e2 * inv; attn[r][3] = e3 * inv;
    }

    float4 o[4][4];
    #pragma unroll
    for (int r = 0; r < 4; r++)
        #pragma unroll
        for (int d = 0; d < 4; d++) o[r][d] = make_float4(0.f, 0.f, 0.f, 0.f);

    #pragma unroll
    for (int c = 0; c < 4; c++) {
        float4 v[4];
        #pragma unroll
        for (int d = 0; d < 4; d++) v[d] = base[c * 96 + 64 + d];
        #pragma unroll
        for (int r = 0; r < 4; r++) {
            float a = attn[r][c];
            #pragma unroll
            for (int d = 0; d < 4; d++) {
                o[r][d].x = fmaf(a, v[d].x, o[r][d].x);
                o[r][d].y = fmaf(a, v[d].y, o[r][d].y);
                o[r][d].z = fmaf(a, v[d].z, o[r][d].z);
                o[r][d].w = fmaf(a, v[d].w, o[r][d].w);
            }
        }
    }

    float4* outp = (float4*)(g_ocat + (size_t)g * 512 + h * 16);
    #pragma unroll
    for (int r = 0; r < 4; r++)
        #pragma unroll
        for (int d = 0; d < 4; d++) outp[r * 32 + d] = o[r][d];
}

// ---------------- GEMM2: ocat[32,512] @ WofT -> out[32,128] per block --------
// block = 256 threads, 32 groups. Thread (tm=t/32, tn=t%32):
// rows tm*4+i (i<4), cols tn + j*32 (j<4) -> 16 accumulators. K chunked by 128.
__global__ void __launch_bounds__(256) out_gemm(float* __restrict__ out)
{
    __shared__ float Os[32 * 128];
    int t  = threadIdx.x;
    int g0 = blockIdx.x * 32;
    int tm = t >> 5;   // 0..7
    int tn = t & 31;   // 0..31

    float acc[4][4];
    #pragma unroll
    for (int i = 0; i < 4; i++)
        #pragma unroll
        for (int j = 0; j < 4; j++) acc[i][j] = 0.f;

    for (int kc = 0; kc < 4; kc++) {
        __syncthreads();
        for (int idx = t; idx < 4096; idx += 256) {
            int m = idx >> 7, e = idx & 127;
            Os[idx] = g_ocat[(size_t)(g0 + m) * 512 + kc * 128 + e];
        }
        __syncthreads();

        const float* Wp = g_WofT + (kc * 128) * 128 + tn;
        #pragma unroll 4
        for (int k = 0; k < 128; k++) {
            float w[4];
            #pragma unroll
            for (int j = 0; j < 4; j++) w[j] = Wp[k * 128 + j * 32];
            #pragma unroll
            for (int i = 0; i < 4; i++) {
                float x = Os[(tm * 4 + i) * 128 + k];
                #pragma unroll
                for (int j = 0; j < 4; j++) acc[i][j] = fmaf(x, w[j], acc[i][j]);
            }
        }
    }

    #pragma unroll
    for (int i = 0; i < 4; i++) {
        size_t rowbase = (size_t)(g0 + tm * 4 + i) * 128;
        #pragma unroll
        for (int j = 0; j < 4; j++) {
            int c = tn + j * 32;
            out[rowbase + c] = acc[i][j] + g_bof[c];
        }
    }
}

// ---------------- launch ----------------
extern "C" void kernel_launch(void* const* d_in, const int* in_sizes, int n_in,
                              void* d_out, int out_size)
{
    const float* node = (const float*)d_in[0];
    const float* sub  = (const float*)d_in[1];
    const float* Wq   = (const float*)d_in[2];
    const float* bq   = (const float*)d_in[3];
    const float* Wk   = (const float*)d_in[4];
    const float* bk   = (const float*)d_in[5];
    const float* Wv   = (const float*)d_in[6];
    const float* bv   = (const float*)d_in[7];
    const float* in_w = (const float*)d_in[8];
    const float* in_b = (const float*)d_in[9];
    const float* out_w = (const float*)d_in[10];
    const float* out_b = (const float*)d_in[11];
    const float* fc_w  = (const float*)d_in[12];
    const float* fc_b  = (const float*)d_in[13];
    float* out = (float*)d_out;

    prep_kernel<<<896, 128>>>(Wq, bq, Wk, bk, Wv, bv, in_w, in_b, out_w, out_b, fc_w, fc_b);
    qkv_gemm<<<NGROUPS / 8, 256>>>(node, sub);
    attn_kernel<<<NGROUPS * 8 / 256, 256>>>();
    out_gemm<<<NGROUPS / 32, 256>>>(out);
}

// round 2
// speedup vs baseline: 1.1476x; 1.1476x over previous
#include <cuda_runtime.h>

// B=8, N=64, T=128, E=128, H=8, R=4, DH=16
#define NGROUPS 65536

// ---------------- scratch (device globals; no allocation allowed) ----------
__device__ float g_WqkvT[128 * 384];            // [k][c] folded qkv weight
__device__ float g_bqkv[384];                   // folded qkv bias
__device__ float g_WofT[512 * 128];             // [c][eo] folded output weight
__device__ float g_bof[128];                    // folded output bias
__device__ float g_ocat[(size_t)NGROUPS * 512]; // attention output (pre out_w)

// ---------------- packed f32x2 helpers ----------------
__device__ __forceinline__ void ffma2(unsigned long long& acc,
                                      unsigned long long a, unsigned long long b) {
    asm("fma.rn.f32x2 %0, %1, %2, %0;" : "+l"(acc) : "l"(a), "l"(b));
}
__device__ __forceinline__ unsigned long long pack2(float x) {
    unsigned long long r;
    asm("mov.b64 %0, {%1, %1};" : "=l"(r) : "f"(x));
    return r;
}
__device__ __forceinline__ float2 unpack2(unsigned long long v) {
    float2 f;
    asm("mov.b64 {%0, %1}, %2;" : "=f"(f.x), "=f"(f.y) : "l"(v));
    return f;
}

// ---------------- weight folding ----------------
__global__ void prep_kernel(const float* __restrict__ Wq, const float* __restrict__ bq,
                            const float* __restrict__ Wk, const float* __restrict__ bk,
                            const float* __restrict__ Wv, const float* __restrict__ bv,
                            const float* __restrict__ in_w, const float* __restrict__ in_b,
                            const float* __restrict__ out_w, const float* __restrict__ out_b,
                            const float* __restrict__ fc_w, const float* __restrict__ fc_b)
{
    int row = blockIdx.x;   // 0..895
    int t   = threadIdx.x;  // 0..127

    if (row < 384) {
        int sub = row >> 7;
        const float* W    = (sub == 0) ? Wq : (sub == 1) ? Wk : Wv;
        const float* bvec = (sub == 0) ? bq : (sub == 1) ? bk : bv;
        const float* iw   = in_w + (size_t)row * 128;
        float acc = 0.f;
        #pragma unroll 4
        for (int e = 0; e < 128; e++)
            acc = fmaf(iw[e], W[e * 128 + t], acc);
        g_WqkvT[t * 384 + row] = acc;
        if (t == 0) {
            float b = in_b[row];
            for (int e = 0; e < 128; e++) b = fmaf(iw[e], bvec[e], b);
            g_bqkv[row] = b;
        }
    } else {
        int idx = row - 384;
        int r  = idx >> 7;
        int eo = idx & 127;
        const float* fw = fc_w + (size_t)eo * 512 + r * 128;
        float acc = 0.f;
        #pragma unroll 4
        for (int f = 0; f < 128; f++)
            acc = fmaf(fw[f], out_w[f * 128 + t], acc);
        g_WofT[(r * 128 + t) * 128 + eo] = acc;
        if (t == 0 && r == 0) {
            float b = fc_b[eo];
            const float* fwa = fc_w + (size_t)eo * 512;
            for (int c = 0; c < 512; c++) b = fmaf(fwa[c], out_b[c & 127], b);
            g_bof[eo] = b;
        }
    }
}

// ---------------- fused: X gather + QKV GEMM + attention -> g_ocat ----------
// block = 256 threads, 8 groups (32 rows of X).
// GEMM phase: thread (tm=t/64, tn=t%64): rows tm*8+i (i<8),
//   col pairs {2tn+j*128, +1} (j<3) -> acc[8][3] packed f32x2.
// Weights staged in smem in k-chunks of 16.
// Attention phase: thread = (g, h, r); qkv lives in smem.
__global__ void __launch_bounds__(256) fused_qkv_attn(const float* __restrict__ node,
                                                      const float* __restrict__ sub)
{
    __shared__ __align__(16) float smem_buf[12288];   // 48 KB
    float* Xs = smem_buf;                              // [32][128] (phase A)
    float* Wc = smem_buf + 4096;                       // [16][384] (phase A)
    // phase B: smem_buf = qkv [32][384]

    int t  = threadIdx.x;
    int g0 = blockIdx.x * 8;

    // gather X: row m = local_g*4 + r; r==0 -> node, else subgraph (stride 3)
    for (int idx = t; idx < 4096; idx += 256) {
        int m = idx >> 7, e = idx & 127;
        int g = g0 + (m >> 2), r = m & 3;
        Xs[idx] = (r == 0) ? node[(size_t)g * 128 + e]
                           : sub[(size_t)g * 384 + e * 3 + (r - 1)];
    }

    int tm = t >> 6;   // 0..3
    int tn = t & 63;   // 0..63

    unsigned long long acc[8][3];
    #pragma unroll
    for (int i = 0; i < 8; i++)
        #pragma unroll
        for (int j = 0; j < 3; j++) acc[i][j] = 0ull;

    for (int kc = 0; kc < 8; kc++) {
        __syncthreads();
        const float* wsrc = g_WqkvT + kc * 6144;
        for (int idx = t; idx < 6144; idx += 256) Wc[idx] = wsrc[idx];
        __syncthreads();

        #pragma unroll 4
        for (int kk = 0; kk < 16; kk++) {
            unsigned long long w[3];
            #pragma unroll
            for (int j = 0; j < 3; j++)
                w[j] = *(const unsigned long long*)&Wc[kk * 384 + 2 * tn + j * 128];
            #pragma unroll
            for (int i = 0; i < 8; i++) {
                unsigned long long xx = pack2(Xs[(tm * 8 + i) * 128 + kc * 16 + kk]);
                #pragma unroll
                for (int j = 0; j < 3; j++) ffma2(acc[i][j], xx, w[j]);
            }
        }
    }
    __syncthreads();

    // store qkv (+bias) into smem: [row 32][384]
    #pragma unroll
    for (int j = 0; j < 3; j++) {
        int c = 2 * tn + j * 128;
        float2 b = *(const float2*)&g_bqkv[c];
        #pragma unroll
        for (int i = 0; i < 8; i++) {
            float2 v = unpack2(acc[i][j]);
            v.x += b.x; v.y += b.y;
            *(float2*)&smem_buf[(tm * 8 + i) * 384 + c] = v;
        }
    }
    __syncthreads();

    // attention: thread -> (g, h, r)
    int g = t >> 5;
    int h = (t >> 2) & 7;
    int r = t & 3;
    const float4* qp = (const float4*)&smem_buf[(g * 4 + r) * 384 + h * 16];

    float4 q[4];
    #pragma unroll
    for (int d = 0; d < 4; d++) q[d] = qp[d];

    float s[4];
    #pragma unroll
    for (int c = 0; c < 4; c++) {
        const float4* kp = (const float4*)&smem_buf[(g * 4 + c) * 384 + 128 + h * 16];
        float a = 0.f;
        #pragma unroll
        for (int d = 0; d < 4; d++) {
            float4 kv = kp[d];
            a = fmaf(q[d].x, kv.x, a);
            a = fmaf(q[d].y, kv.y, a);
            a = fmaf(q[d].z, kv.z, a);
            a = fmaf(q[d].w, kv.w, a);
        }
        s[c] = a * 0.25f;   // 1/sqrt(DH)
    }

    float m  = fmaxf(fmaxf(s[0], s[1]), fmaxf(s[2], s[3]));
    float e0 = __expf(s[0] - m), e1 = __expf(s[1] - m);
    float e2 = __expf(s[2] - m), e3 = __expf(s[3] - m);
    float inv = 1.f / (e0 + e1 + e2 + e3);
    float a0 = e0 * inv, a1 = e1 * inv, a2 = e2 * inv, a3 = e3 * inv;

    float4 o[4];
    #pragma unroll
    for (int d = 0; d < 4; d++) o[d] = make_float4(0.f, 0.f, 0.f, 0.f);

    #pragma unroll
    for (int c = 0; c < 4; c++) {
        float a = (c == 0) ? a0 : (c == 1) ? a1 : (c == 2) ? a2 : a3;
        const float4* vp = (const float4*)&smem_buf[(g * 4 + c) * 384 + 256 + h * 16];
        #pragma unroll
        for (int d = 0; d < 4; d++) {
            float4 vv = vp[d];
            o[d].x = fmaf(a, vv.x, o[d].x);
            o[d].y = fmaf(a, vv.y, o[d].y);
            o[d].z = fmaf(a, vv.z, o[d].z);
            o[d].w = fmaf(a, vv.w, o[d].w);
        }
    }

    float4* outp = (float4*)&g_ocat[(size_t)(g0 + g) * 512 + r * 128 + h * 16];
    #pragma unroll
    for (int d = 0; d < 4; d++) outp[d] = o[d];
}

// ---------------- GEMM2: ocat[64,512] @ WofT -> out[64,128] per block --------
// block = 256 threads, 64 groups. Thread (tm=t/16, tn=t%16):
// rows tm*4+i (i<4), col pairs {2tn+p*32, +1} (p<4) -> acc[4][4] f32x2.
// K chunked by 16; Os padded stride 17 to avoid bank conflicts.
__global__ void __launch_bounds__(256) out_gemm(float* __restrict__ out)
{
    __shared__ __align__(16) float Os[64 * 17];   // 4352 B
    __shared__ __align__(16) float Wc[16 * 128];  // 8 KB

    int t  = threadIdx.x;
    int g0 = blockIdx.x * 64;
    int tm = t >> 4;   // 0..15
    int tn = t & 15;   // 0..15

    unsigned long long acc[4][4];
    #pragma unroll
    for (int i = 0; i < 4; i++)
        #pragma unroll
        for (int p = 0; p < 4; p++) acc[i][p] = 0ull;

    for (int kc = 0; kc < 32; kc++) {
        __syncthreads();
        for (int idx = t; idx < 1024; idx += 256) {
            int m = idx >> 4, kk = idx & 15;
            Os[m * 17 + kk] = g_ocat[(size_t)(g0 + m) * 512 + kc * 16 + kk];
        }
        const float* wsrc = g_WofT + kc * 2048;
        for (int idx = t; idx < 2048; idx += 256) Wc[idx] = wsrc[idx];
        __syncthreads();

        #pragma unroll 4
        for (int kk = 0; kk < 16; kk++) {
            unsigned long long w[4];
            #pragma unroll
            for (int p = 0; p < 4; p++)
                w[p] = *(const unsigned long long*)&Wc[kk * 128 + 2 * tn + p * 32];
            #pragma unroll
            for (int i = 0; i < 4; i++) {
                unsigned long long xx = pack2(Os[(tm * 4 + i) * 17 + kk]);
                #pragma unroll
                for (int p = 0; p < 4; p++) ffma2(acc[i][p], xx, w[p]);
            }
        }
    }

    #pragma unroll
    for (int p = 0; p < 4; p++) {
        int c = 2 * tn + p * 32;
        float2 b = *(const float2*)&g_bof[c];
        #pragma unroll
        for (int i = 0; i < 4; i++) {
            float2 v = unpack2(acc[i][p]);
            v.x += b.x; v.y += b.y;
            *(float2*)&out[(size_t)(g0 + tm * 4 + i) * 128 + c] = v;
        }
    }
}

// ---------------- launch ----------------
extern "C" void kernel_launch(void* const* d_in, const int* in_sizes, int n_in,
                              void* d_out, int out_size)
{
    const float* node = (const float*)d_in[0];
    const float* sub  = (const float*)d_in[1];
    const float* Wq   = (const float*)d_in[2];
    const float* bq   = (const float*)d_in[3];
    const float* Wk   = (const float*)d_in[4];
    const float* bk   = (const float*)d_in[5];
    const float* Wv   = (const float*)d_in[6];
    const float* bv   = (const float*)d_in[7];
    const float* in_w = (const float*)d_in[8];
    const float* in_b = (const float*)d_in[9];
    const float* out_w = (const float*)d_in[10];
    const float* out_b = (const float*)d_in[11];
    const float* fc_w  = (const float*)d_in[12];
    const float* fc_b  = (const float*)d_in[13];
    float* out = (float*)d_out;

    prep_kernel<<<896, 128>>>(Wq, bq, Wk, bk, Wv, bv, in_w, in_b, out_w, out_b, fc_w, fc_b);
    fused_qkv_attn<<<NGROUPS / 8, 256>>>(node, sub);
    out_gemm<<<NGROUPS / 64, 256>>>(out);
}

// round 3
// speedup vs baseline: 1.7463x; 1.5217x over previous
#include <cuda_runtime.h>
#include <cstdint>

// B=8, N=64, T=128, E=128, H=8, R=4, DH=16
#define NGROUPS 65536

// ---------------- scratch (device globals) ----------------
// B-fragment layouts for mma.sync.m16n8k8.tf32 (b0: k=lane%4, n=lane/4; b1: k+4)
__device__ uint32_t g_Wqkv_frag[16 * 48 * 32 * 2];  // [kt][nt][lane][2], K=128,N=384
__device__ float    g_bqkv[384];
__device__ uint32_t g_Wof_frag[64 * 16 * 32 * 2];   // [kt][nt][lane][2], K=512,N=128
__device__ float    g_bof[128];
__device__ float    g_ocat[(size_t)NGROUPS * 512];  // attention output (pre out_w)

// ---------------- helpers ----------------
__device__ __forceinline__ uint32_t f2tf32(float x) {
    uint32_t u;
    asm("cvt.rna.tf32.f32 %0, %1;" : "=r"(u) : "f"(x));
    return u;
}
__device__ __forceinline__ void mma_tf32(float c[4], const uint32_t a[4], const uint32_t b[2]) {
    asm volatile(
        "mma.sync.aligned.m16n8k8.row.col.f32.tf32.tf32.f32 "
        "{%0,%1,%2,%3}, {%4,%5,%6,%7}, {%8,%9}, {%0,%1,%2,%3};"
        : "+f"(c[0]), "+f"(c[1]), "+f"(c[2]), "+f"(c[3])
        : "r"(a[0]), "r"(a[1]), "r"(a[2]), "r"(a[3]), "r"(b[0]), "r"(b[1]));
}
__device__ __forceinline__ float warp_reduce(float v) {
    #pragma unroll
    for (int o = 16; o > 0; o >>= 1) v += __shfl_xor_sync(0xffffffffu, v, o);
    return v;
}

// ---------------- weight folding (writes fragment layout) ----------------
// blocks 0..383  : qkv fold. n = blockIdx, k = t.
//   B[k][n] = sum_e in_w[n*128+e] * W{sub}[e*128+k],  sub = n>>7
// blocks 384..895: output fold. idx = blockIdx-384 = (r,eo); k = r*128+t, n = eo.
//   B[k][n] = sum_f fc_w[eo*512 + r*128 + f] * out_w[f*128 + t]
__global__ void prep_kernel(const float* __restrict__ Wq, const float* __restrict__ bq,
                            const float* __restrict__ Wk, const float* __restrict__ bk,
                            const float* __restrict__ Wv, const float* __restrict__ bv,
                            const float* __restrict__ in_w, const float* __restrict__ in_b,
                            const float* __restrict__ out_w, const float* __restrict__ out_b,
                            const float* __restrict__ fc_w, const float* __restrict__ fc_b)
{
    int row = blockIdx.x;
    int t   = threadIdx.x;  // 0..127

    if (row < 384) {
        int n = row;
        int sub = n >> 7;
        const float* W    = (sub == 0) ? Wq : (sub == 1) ? Wk : Wv;
        const float* bvec = (sub == 0) ? bq : (sub == 1) ? bk : bv;
        const float* iw   = in_w + (size_t)n * 128;
        float a0 = 0.f, a1 = 0.f, a2 = 0.f, a3 = 0.f;
        #pragma unroll 8
        for (int e = 0; e < 128; e += 4) {
            a0 = fmaf(iw[e + 0], W[(e + 0) * 128 + t], a0);
            a1 = fmaf(iw[e + 1], W[(e + 1) * 128 + t], a1);
            a2 = fmaf(iw[e + 2], W[(e + 2) * 128 + t], a2);
            a3 = fmaf(iw[e + 3], W[(e + 3) * 128 + t], a3);
        }
        float val = (a0 + a1) + (a2 + a3);
        int k = t;
        int kt = k >> 3, jj = (k >> 2) & 1;
        int lane = ((n & 7) << 2) | (k & 3);
        int nt = n >> 3;
        g_Wqkv_frag[((kt * 48 + nt) * 32 + lane) * 2 + jj] = f2tf32(val);

        if (t < 32) {  // bias via one warp
            float p = 0.f;
            for (int e = t; e < 128; e += 32) p = fmaf(iw[e], bvec[e], p);
            p = warp_reduce(p);
            if (t == 0) g_bqkv[n] = p + in_b[n];
        }
    } else {
        int idx = row - 384;
        int r  = idx >> 7;
        int eo = idx & 127;
        const float* fw = fc_w + (size_t)eo * 512 + r * 128;
        float a0 = 0.f, a1 = 0.f, a2 = 0.f, a3 = 0.f;
        #pragma unroll 8
        for (int f = 0; f < 128; f += 4) {
            a0 = fmaf(fw[f + 0], out_w[(f + 0) * 128 + t], a0);
            a1 = fmaf(fw[f + 1], out_w[(f + 1) * 128 + t], a1);
            a2 = fmaf(fw[f + 2], out_w[(f + 2) * 128 + t], a2);
            a3 = fmaf(fw[f + 3], out_w[(f + 3) * 128 + t], a3);
        }
        float val = (a0 + a1) + (a2 + a3);
        int k = r * 128 + t, n = eo;
        int kt = k >> 3, jj = (k >> 2) & 1;
        int lane = ((n & 7) << 2) | (k & 3);
        int nt = n >> 3;
        g_Wof_frag[((kt * 16 + nt) * 32 + lane) * 2 + jj] = f2tf32(val);

        if (r == 0 && t < 32) {
            const float* fwa = fc_w + (size_t)eo * 512;
            float p = 0.f;
            for (int c = t; c < 512; c += 32) p = fmaf(fwa[c], out_b[c & 127], p);
            p = warp_reduce(p);
            if (t == 0) g_bof[eo] = p + fc_b[eo];
        }
    }
}

// ---------------- fused: gather + tf32 QKV GEMM + attention -> g_ocat -------
// 512 threads (16 warps), 16 groups (64 rows), N=384, K=128.
// warp w: mtile wm=w&3 (rows wm*16..), n-quarter wn=w>>2 (ntiles wn*12..+12).
// smem (dynamic, 100352 B):
//   phase A: Xfrag u32[4mt][16kt][32][4] @0 (32KB), Wc u32[4kt][48nt][32][2] @32KB (48KB)
//   phase B: qkv f32[64][392]
#define QS_STRIDE 392
__global__ void __launch_bounds__(512) fused_qkv_attn(const float* __restrict__ node,
                                                      const float* __restrict__ sub)
{
    extern __shared__ __align__(16) char smem[];
    uint32_t* Xfrag = (uint32_t*)smem;            // 8192 u32
    uint32_t* Wc    = (uint32_t*)(smem + 32768);  // 12288 u32
    float*    qs    = (float*)smem;               // 64*392 floats

    int t    = threadIdx.x;
    int g0   = blockIdx.x * 16;
    int w    = t >> 5;
    int lane = t & 31;
    int wm   = w & 3;
    int wn   = w >> 2;

    // gather X into A-fragment layout (tf32)
    for (int idx = t; idx < 8192; idx += 512) {
        int j    = idx & 3;
        int lidx = (idx >> 2) & 31;
        int kt   = (idx >> 7) & 15;
        int mt   = idx >> 11;
        int rowl = mt * 16 + (lidx >> 2) + (j & 1) * 8;
        int k    = kt * 8 + (lidx & 3) + (j >> 1) * 4;
        int g    = g0 + (rowl >> 2), r = rowl & 3;
        float v  = (r == 0) ? node[(size_t)g * 128 + k]
                            : sub[(size_t)g * 384 + k * 3 + (r - 1)];
        Xfrag[idx] = f2tf32(v);
    }

    float c[12][4];
    #pragma unroll
    for (int n = 0; n < 12; n++)
        #pragma unroll
        for (int j = 0; j < 4; j++) c[n][j] = 0.f;

    for (int s = 0; s < 4; s++) {           // 4 stages of 4 ktiles
        __syncthreads();
        const uint4* wsrc = (const uint4*)(g_Wqkv_frag + s * 12288);
        uint4* wdst = (uint4*)Wc;
        for (int idx = t; idx < 3072; idx += 512) wdst[idx] = wsrc[idx];
        __syncthreads();

        #pragma unroll
        for (int kl = 0; kl < 4; kl++) {
            int ktile = s * 4 + kl;
            uint32_t a[4];
            *(uint4*)a = *(const uint4*)&Xfrag[((wm * 16 + ktile) * 32 + lane) * 4];
            #pragma unroll
            for (int n = 0; n < 12; n++) {
                uint32_t b[2];
                *(uint2*)b = *(const uint2*)&Wc[((kl * 48 + wn * 12 + n) * 32 + lane) * 2];
                mma_tf32(c[n], a, b);
            }
        }
    }
    __syncthreads();   // all mma reads of Xfrag/Wc done before qs overwrite

    // epilogue: +bias, store to qs
    {
        int row0 = wm * 16 + (lane >> 2);
        #pragma unroll
        for (int n = 0; n < 12; n++) {
            int col = (wn * 12 + n) * 8 + (lane & 3) * 2;
            float2 bb = *(const float2*)&g_bqkv[col];
            float2 v0 = make_float2(c[n][0] + bb.x, c[n][1] + bb.y);
            float2 v1 = make_float2(c[n][2] + bb.x, c[n][3] + bb.y);
            *(float2*)&qs[row0 * QS_STRIDE + col]       = v0;
            *(float2*)&qs[(row0 + 8) * QS_STRIDE + col] = v1;
        }
    }
    __syncthreads();

    // attention: thread = (g, h, r)
    {
        int g = t >> 5;          // 0..15
        int h = (t >> 2) & 7;
        int r = t & 3;
        const float* rowbase = qs + (size_t)(g * 4) * QS_STRIDE + h * 16;

        float4 q[4];
        const float4* qp = (const float4*)(rowbase + r * QS_STRIDE);
        #pragma unroll
        for (int d = 0; d < 4; d++) q[d] = qp[d];

        float s[4];
        #pragma unroll
        for (int cc = 0; cc < 4; cc++) {
            const float4* kp = (const float4*)(rowbase + cc * QS_STRIDE + 128);
            float a = 0.f;
            #pragma unroll
            for (int d = 0; d < 4; d++) {
                float4 kv = kp[d];
                a = fmaf(q[d].x, kv.x, a);
                a = fmaf(q[d].y, kv.y, a);
                a = fmaf(q[d].z, kv.z, a);
                a = fmaf(q[d].w, kv.w, a);
            }
            s[cc] = a * 0.25f;
        }

        float m  = fmaxf(fmaxf(s[0], s[1]), fmaxf(s[2], s[3]));
        float e0 = __expf(s[0] - m), e1 = __expf(s[1] - m);
        float e2 = __expf(s[2] - m), e3 = __expf(s[3] - m);
        float inv = 1.f / (e0 + e1 + e2 + e3);
        float aw[4] = {e0 * inv, e1 * inv, e2 * inv, e3 * inv};

        float4 o[4];
        #pragma unroll
        for (int d = 0; d < 4; d++) o[d] = make_float4(0.f, 0.f, 0.f, 0.f);
        #pragma unroll
        for (int cc = 0; cc < 4; cc++) {
            const float4* vp = (const float4*)(rowbase + cc * QS_STRIDE + 256);
            float a = aw[cc];
            #pragma unroll
            for (int d = 0; d < 4; d++) {
                float4 vv = vp[d];
                o[d].x = fmaf(a, vv.x, o[d].x);
                o[d].y = fmaf(a, vv.y, o[d].y);
                o[d].z = fmaf(a, vv.z, o[d].z);
                o[d].w = fmaf(a, vv.w, o[d].w);
            }
        }

        float4* outp = (float4*)&g_ocat[(size_t)(g0 + g) * 512 + r * 128 + h * 16];
        #pragma unroll
        for (int d = 0; d < 4; d++) outp[d] = o[d];
    }
}

// ---------------- GEMM2: ocat[64,512] @ Wof -> out[64,128], tf32 MMA --------
// 256 threads (8 warps). warp w: mtile wm=w&3, n-half wn=w>>2 (8 ntiles each).
#define AS_STRIDE 36
__global__ void __launch_bounds__(256) out_gemm(float* __restrict__ out)
{
    __shared__ __align__(16) uint32_t As[64 * AS_STRIDE];  // tf32 A chunk [64][32] padded
    __shared__ __align__(16) uint32_t Wofc[4 * 16 * 64];   // 4096 u32

    int t    = threadIdx.x;
    int g0   = blockIdx.x * 64;
    int w    = t >> 5;
    int lane = t & 31;
    int wm   = w & 3;
    int wn   = w >> 2;

    float c[8][4];
    #pragma unroll
    for (int n = 0; n < 8; n++)
        #pragma unroll
        for (int j = 0; j < 4; j++) c[n][j] = 0.f;

    for (int s = 0; s < 16; s++) {        // 16 stages of 4 ktiles (k32)
        __syncthreads();
        for (int idx = t; idx < 2048; idx += 256) {
            int m = idx >> 5, kk = idx & 31;
            As[m * AS_STRIDE + kk] = f2tf32(g_ocat[(size_t)(g0 + m) * 512 + s * 32 + kk]);
        }
        const uint4* wsrc = (const uint4*)(g_Wof_frag + s * 4096);
        uint4* wdst = (uint4*)Wofc;
        for (int idx = t; idx < 1024; idx += 256) wdst[idx] = wsrc[idx];
        __syncthreads();

        #pragma unroll
        for (int kt = 0; kt < 4; kt++) {
            int row = wm * 16 + (lane >> 2);
            int kb  = kt * 8 + (lane & 3);
            uint32_t a[4];
            a[0] = As[row * AS_STRIDE + kb];
            a[1] = As[(row + 8) * AS_STRIDE + kb];
            a[2] = As[row * AS_STRIDE + kb + 4];
            a[3] = As[(row + 8) * AS_STRIDE + kb + 4];
            #pragma unroll
            for (int n = 0; n < 8; n++) {
                uint32_t b[2];
                *(uint2*)b = *(const uint2*)&Wofc[((kt * 16 + wn * 8 + n) * 32 + lane) * 2];
                mma_tf32(c[n], a, b);
            }
        }
    }

    int row0 = g0 + wm * 16 + (lane >> 2);
    #pragma unroll
    for (int n = 0; n < 8; n++) {
        int col = (wn * 8 + n) * 8 + (lane & 3) * 2;
        float2 bb = *(const float2*)&g_bof[col];
        float2 v0 = make_float2(c[n][0] + bb.x, c[n][1] + bb.y);
        float2 v1 = make_float2(c[n][2] + bb.x, c[n][3] + bb.y);
        *(float2*)&out[(size_t)row0 * 128 + col]       = v0;
        *(float2*)&out[(size_t)(row0 + 8) * 128 + col] = v1;
    }
}

// ---------------- launch ----------------
extern "C" void kernel_launch(void* const* d_in, const int* in_sizes, int n_in,
                              void* d_out, int out_size)
{
    const float* node = (const float*)d_in[0];
    const float* sub  = (const float*)d_in[1];
    const float* Wq   = (const float*)d_in[2];
    const float* bq   = (const float*)d_in[3];
    const float* Wk   = (const float*)d_in[4];
    const float* bk   = (const float*)d_in[5];
    const float* Wv   = (const float*)d_in[6];
    const float* bv   = (const float*)d_in[7];
    const float* in_w = (const float*)d_in[8];
    const float* in_b = (const float*)d_in[9];
    const float* out_w = (const float*)d_in[10];
    const float* out_b = (const float*)d_in[11];
    const float* fc_w  = (const float*)d_in[12];
    const float* fc_b  = (const float*)d_in[13];
    float* out = (float*)d_out;

    static int smem_set = 0;
    if (!smem_set) {
        cudaFuncSetAttribute(fused_qkv_attn, cudaFuncAttributeMaxDynamicSharedMemorySize,
                             64 * QS_STRIDE * 4);
        smem_set = 1;
    }

    prep_kernel<<<896, 128>>>(Wq, bq, Wk, bk, Wv, bv, in_w, in_b, out_w, out_b, fc_w, fc_b);
    fused_qkv_attn<<<NGROUPS / 16, 512, 64 * QS_STRIDE * 4>>>(node, sub);
    out_gemm<<<NGROUPS / 64, 256>>>(out);
}

// round 5
// speedup vs baseline: 3.2230x; 1.8456x over previous
#include <cuda_runtime.h>
#include <cuda_fp16.h>
#include <cstdint>

// B=8, N=64, T=128, E=128, H=8, R=4, DH=16
#define NGROUPS 65536

// ---------------- device scratch ----------------
// fp16 B-fragment layouts for mma.sync.m16n8k16 (row.col):
//   b reg j (=k8 half), lane = (n&7)*4 + ((k>>1)&3), half = k&1, ktile = k>>4
__device__ __half g_Wqkv_frag[8 * 48 * 32 * 4];   // K=128 (8 kt), N=384 (48 nt): 96KB
__device__ float  g_bqkv[384];
__device__ __half g_Wof_frag[32 * 16 * 32 * 4];   // K=512 (32 kt), N=128 (16 nt): 128KB
__device__ float  g_bof[128];
__device__ __half g_ocat[(size_t)NGROUPS * 512];  // attention output (pre out_w), fp16

// ---------------- helpers ----------------
__device__ __forceinline__ void mma_f16(float c[4], const uint32_t a[4], const uint32_t b[2]) {
    asm volatile(
        "mma.sync.aligned.m16n8k16.row.col.f32.f16.f16.f32 "
        "{%0,%1,%2,%3}, {%4,%5,%6,%7}, {%8,%9}, {%0,%1,%2,%3};"
        : "+f"(c[0]), "+f"(c[1]), "+f"(c[2]), "+f"(c[3])
        : "r"(a[0]), "r"(a[1]), "r"(a[2]), "r"(a[3]), "r"(b[0]), "r"(b[1]));
}
__device__ __forceinline__ float warp_red(float v) {
    #pragma unroll
    for (int o = 16; o > 0; o >>= 1) v += __shfl_xor_sync(0xffffffffu, v, o);
    return v;
}

// ---------------- weight folding -> fp16 fragment layouts ----------------
__global__ void prep_kernel(const float* __restrict__ Wq, const float* __restrict__ bq,
                            const float* __restrict__ Wk, const float* __restrict__ bk,
                            const float* __restrict__ Wv, const float* __restrict__ bv,
                            const float* __restrict__ in_w, const float* __restrict__ in_b,
                            const float* __restrict__ out_w, const float* __restrict__ out_b,
                            const float* __restrict__ fc_w, const float* __restrict__ fc_b)
{
    int row = blockIdx.x;
    int t   = threadIdx.x;  // 0..127

    if (row < 384) {
        int n = row, sub = n >> 7;
        const float* W    = (sub == 0) ? Wq : (sub == 1) ? Wk : Wv;
        const float* bvec = (sub == 0) ? bq : (sub == 1) ? bk : bv;
        const float* iw   = in_w + (size_t)n * 128;
        float a0 = 0.f, a1 = 0.f, a2 = 0.f, a3 = 0.f;
        #pragma unroll 8
        for (int e = 0; e < 128; e += 4) {
            a0 = fmaf(iw[e + 0], W[(e + 0) * 128 + t], a0);
            a1 = fmaf(iw[e + 1], W[(e + 1) * 128 + t], a1);
            a2 = fmaf(iw[e + 2], W[(e + 2) * 128 + t], a2);
            a3 = fmaf(iw[e + 3], W[(e + 3) * 128 + t], a3);
        }
        float val = (a0 + a1) + (a2 + a3);
        int k = t;
        int kt = k >> 4, j = (k >> 3) & 1, hh = k & 1;
        int lane = ((n & 7) << 2) | ((k >> 1) & 3);
        int nt = n >> 3;
        g_Wqkv_frag[(((kt * 48 + nt) * 32 + lane) * 2 + j) * 2 + hh] = __float2half_rn(val);

        if (t < 32) {
            float p = 0.f;
            for (int e = t; e < 128; e += 32) p = fmaf(iw[e], bvec[e], p);
            p = warp_red(p);
            if (t == 0) g_bqkv[n] = p + in_b[n];
        }
    } else {
        int idx = row - 384;
        int r  = idx >> 7;
        int eo = idx & 127;
        const float* fw = fc_w + (size_t)eo * 512 + r * 128;
        float a0 = 0.f, a1 = 0.f, a2 = 0.f, a3 = 0.f;
        #pragma unroll 8
        for (int f = 0; f < 128; f += 4) {
            a0 = fmaf(fw[f + 0], out_w[(f + 0) * 128 + t], a0);
            a1 = fmaf(fw[f + 1], out_w[(f + 1) * 128 + t], a1);
            a2 = fmaf(fw[f + 2], out_w[(f + 2) * 128 + t], a2);
            a3 = fmaf(fw[f + 3], out_w[(f + 3) * 128 + t], a3);
        }
        float val = (a0 + a1) + (a2 + a3);
        int n = eo, k = r * 128 + t;
        int kt = k >> 4, j = (k >> 3) & 1, hh = k & 1;
        int lane = ((n & 7) << 2) | ((k >> 1) & 3);
        int nt = n >> 3;
        g_Wof_frag[(((kt * 16 + nt) * 32 + lane) * 2 + j) * 2 + hh] = __float2half_rn(val);

        if (r == 0 && t < 32) {
            const float* fwa = fc_w + (size_t)eo * 512;
            float p = 0.f;
            for (int c = t; c < 512; c += 32) p = fmaf(fwa[c], out_b[c & 127], p);
            p = warp_red(p);
            if (t == 0) g_bof[eo] = p + fc_b[eo];
        }
    }
}

// ---------------- fused: gather + fp16 QKV GEMM + attention -> g_ocat -------
// 512 threads (16 warps), 16 groups (64 rows), N=384, K=128.
// warp w: mtile wm=w&3, n-quarter wn=w>>2 (12 ntiles each).
// smem (dynamic, 101888 B):
//   phase A: Xfrag u32[4mt][8kt][32][4] @0 (16KB), Wc u32 double-buf 2x6144 @16KB
//   phase B: qs f32[64][392] @0
//   bias f32[384] @100352 (both phases)
#define QS_STRIDE 392
#define G1_SMEM (100352 + 1536)
__global__ void __launch_bounds__(512) fused_qkv_attn(const float* __restrict__ node,
                                                      const float* __restrict__ sub)
{
    extern __shared__ __align__(16) char smem[];
    uint32_t* Xf  = (uint32_t*)smem;            // 4096 u32
    uint32_t* Wc  = (uint32_t*)(smem + 16384);  // 2 x 6144 u32
    float*    qs  = (float*)smem;
    float*    bsm = (float*)(smem + 100352);

    int t    = threadIdx.x;
    int g0   = blockIdx.x * 16;
    int w    = t >> 5;
    int lane = t & 31;
    int wm   = w & 3;
    int wn   = w >> 2;

    for (int i = t; i < 384; i += 512) bsm[i] = g_bqkv[i];

    // gather X into fp16 A-fragment layout
    for (int idx = t; idx < 4096; idx += 512) {
        int j  = idx & 3;
        int ln = (idx >> 2) & 31;
        int kt = (idx >> 7) & 7;
        int mt = idx >> 10;
        int rowl = mt * 16 + (ln >> 2) + (j & 1) * 8;
        int k0   = kt * 16 + (ln & 3) * 2 + ((j >> 1) & 1) * 8;
        int g = g0 + (rowl >> 2), r = rowl & 3;
        float x0, x1;
        if (r == 0) {
            float2 v = *(const float2*)&node[(size_t)g * 128 + k0];
            x0 = v.x; x1 = v.y;
        } else {
            const float* s = &sub[(size_t)g * 384 + k0 * 3 + (r - 1)];
            x0 = s[0]; x1 = s[3];
        }
        __half2 hv = __floats2half2_rn(x0, x1);
        Xf[idx] = *(uint32_t*)&hv;
    }

    float c[12][4];
    #pragma unroll
    for (int n = 0; n < 12; n++)
        #pragma unroll
        for (int jj = 0; jj < 4; jj++) c[n][jj] = 0.f;

    // stage 0 copy (2 ktiles = 6144 u32 = 1536 uint4)
    {
        const uint4* src = (const uint4*)g_Wqkv_frag;
        uint4* dst = (uint4*)Wc;
        for (int i = t; i < 1536; i += 512) dst[i] = src[i];
    }
    __syncthreads();

    #pragma unroll 1
    for (int s = 0; s < 4; s++) {
        uint32_t* cur = Wc + (s & 1) * 6144;
        if (s < 3) {
            const uint4* src = (const uint4*)g_Wqkv_frag + (s + 1) * 1536;
            uint4* dst = (uint4*)(Wc + ((s + 1) & 1) * 6144);
            for (int i = t; i < 1536; i += 512) dst[i] = src[i];
        }
        #pragma unroll
        for (int kl = 0; kl < 2; kl++) {
            int kt = s * 2 + kl;
            uint32_t a[4];
            *(uint4*)a = *(const uint4*)&Xf[((wm * 8 + kt) * 32 + lane) * 4];
            #pragma unroll
            for (int n = 0; n < 12; n++) {
                uint32_t b[2];
                *(uint2*)b = *(const uint2*)&cur[((kl * 48 + wn * 12 + n) * 32 + lane) * 2];
                mma_f16(c[n], a, b);
            }
        }
        __syncthreads();
    }

    // epilogue: +bias, store qkv to qs
    {
        int row0 = wm * 16 + (lane >> 2);
        #pragma unroll
        for (int n = 0; n < 12; n++) {
            int col = (wn * 12 + n) * 8 + (lane & 3) * 2;
            float2 bb = *(const float2*)&bsm[col];
            *(float2*)&qs[row0 * QS_STRIDE + col] =
                make_float2(c[n][0] + bb.x, c[n][1] + bb.y);
            *(float2*)&qs[(row0 + 8) * QS_STRIDE + col] =
                make_float2(c[n][2] + bb.x, c[n][3] + bb.y);
        }
    }
    __syncthreads();

    // attention: thread = (g, h, r)
    {
        int g = t >> 5;
        int h = (t >> 2) & 7;
        int r = t & 3;
        const float* rowbase = qs + (size_t)(g * 4) * QS_STRIDE + h * 16;

        float4 q[4];
        const float4* qp = (const float4*)(rowbase + r * QS_STRIDE);
        #pragma unroll
        for (int d = 0; d < 4; d++) q[d] = qp[d];

        float s[4];
        #pragma unroll
        for (int cc = 0; cc < 4; cc++) {
            const float4* kp = (const float4*)(rowbase + cc * QS_STRIDE + 128);
            float a = 0.f;
            #pragma unroll
            for (int d = 0; d < 4; d++) {
                float4 kv = kp[d];
                a = fmaf(q[d].x, kv.x, a);
                a = fmaf(q[d].y, kv.y, a);
                a = fmaf(q[d].z, kv.z, a);
                a = fmaf(q[d].w, kv.w, a);
            }
            s[cc] = a * 0.25f;
        }

        float m  = fmaxf(fmaxf(s[0], s[1]), fmaxf(s[2], s[3]));
        float e0 = __expf(s[0] - m), e1 = __expf(s[1] - m);
        float e2 = __expf(s[2] - m), e3 = __expf(s[3] - m);
        float inv = 1.f / (e0 + e1 + e2 + e3);
        float aw[4] = {e0 * inv, e1 * inv, e2 * inv, e3 * inv};

        float o[16];
        #pragma unroll
        for (int d = 0; d < 16; d++) o[d] = 0.f;
        #pragma unroll
        for (int cc = 0; cc < 4; cc++) {
            const float* vp = rowbase + cc * QS_STRIDE + 256;
            float a = aw[cc];
            #pragma unroll
            for (int d = 0; d < 16; d++) o[d] = fmaf(a, vp[d], o[d]);
        }

        __half2 oh[8];
        #pragma unroll
        for (int jj = 0; jj < 8; jj++) oh[jj] = __floats2half2_rn(o[2 * jj], o[2 * jj + 1]);
        __half* dst = &g_ocat[(size_t)(g0 + g) * 512 + r * 128 + h * 16];
        *(uint4*)dst       = *(uint4*)&oh[0];
        *(uint4*)(dst + 8) = *(uint4*)&oh[4];
    }
}

// ---------------- GEMM2: ocat[64,512](fp16) @ Wof -> out[64,128], fp16 MMA ---
// 256 threads (8 warps). warp w: mtile wm=w&3, n-half wn=w>>2 (8 ntiles each).
// smem (dynamic, 51712 B): Wc double 2x16KB @0, As double 2x9216 @32768, bias @51200
#define AS_STRIDE 72   // halves, conflict-free (36 words/row -> bank = 4*row+c)
#define G2_SMEM 51712
__global__ void __launch_bounds__(256) out_gemm(float* __restrict__ out)
{
    extern __shared__ __align__(16) char smem[];
    uint32_t* Wc  = (uint32_t*)smem;                 // 2 x 4096 u32
    __half*   As  = (__half*)(smem + 32768);         // 2 x 64*72 halves
    float*    bsm = (float*)(smem + 51200);

    int t    = threadIdx.x;
    int g0   = blockIdx.x * 64;
    int w    = t >> 5;
    int lane = t & 31;
    int wm   = w & 3;
    int wn   = w >> 2;

    if (t < 128) bsm[t] = g_bof[t];

    float c[8][4];
    #pragma unroll
    for (int n = 0; n < 8; n++)
        #pragma unroll
        for (int jj = 0; jj < 4; jj++) c[n][jj] = 0.f;

    // stage loader: stage s covers k = s*64 .. s*64+63 (4 ktiles of k16)
    auto load_stage = [&](int s, int buf) {
        // A: 64 rows x 64 halves
        __half* as = As + buf * (64 * AS_STRIDE);
        for (int idx = t; idx < 512; idx += 256) {
            int row = idx >> 3, k8 = idx & 7;
            uint4 v = *(const uint4*)&g_ocat[(size_t)(g0 + row) * 512 + s * 64 + k8 * 8];
            uint32_t* d = (uint32_t*)&as[row * AS_STRIDE + k8 * 8];
            d[0] = v.x; d[1] = v.y; d[2] = v.z; d[3] = v.w;
        }
        // B: 4 ktiles x 16 nt x 64 u32 = 4096 u32 = 1024 uint4
        const uint4* src = (const uint4*)g_Wof_frag + s * 1024;
        uint4* dst = (uint4*)(Wc + buf * 4096);
        for (int i = t; i < 1024; i += 256) dst[i] = src[i];
    };

    load_stage(0, 0);
    __syncthreads();

    #pragma unroll 1
    for (int s = 0; s < 8; s++) {
        const __half* as = As + (s & 1) * (64 * AS_STRIDE);
        const uint32_t* wc = Wc + (s & 1) * 4096;
        if (s < 7) load_stage(s + 1, (s + 1) & 1);

        int row = wm * 16 + (lane >> 2);
        int c2  = (lane & 3) * 2;
        #pragma unroll
        for (int kl = 0; kl < 4; kl++) {
            uint32_t a[4];
            a[0] = *(const uint32_t*)&as[row * AS_STRIDE + kl * 16 + c2];
            a[1] = *(const uint32_t*)&as[(row + 8) * AS_STRIDE + kl * 16 + c2];
            a[2] = *(const uint32_t*)&as[row * AS_STRIDE + kl * 16 + c2 + 8];
            a[3] = *(const uint32_t*)&as[(row + 8) * AS_STRIDE + kl * 16 + c2 + 8];
            #pragma unroll
            for (int n = 0; n < 8; n++) {
                uint32_t b[2];
                *(uint2*)b = *(const uint2*)&wc[((kl * 16 + wn * 8 + n) * 32 + lane) * 2];
                mma_f16(c[n], a, b);
            }
        }
        __syncthreads();
    }

    int row0 = g0 + wm * 16 + (lane >> 2);
    #pragma unroll
    for (int n = 0; n < 8; n++) {
        int col = (wn * 8 + n) * 8 + (lane & 3) * 2;
        float2 bb = *(const float2*)&bsm[col];
        *(float2*)&out[(size_t)row0 * 128 + col] =
            make_float2(c[n][0] + bb.x, c[n][1] + bb.y);
        *(float2*)&out[(size_t)(row0 + 8) * 128 + col] =
            make_float2(c[n][2] + bb.x, c[n][3] + bb.y);
    }
}

// ---------------- launch ----------------
extern "C" void kernel_launch(void* const* d_in, const int* in_sizes, int n_in,
                              void* d_out, int out_size)
{
    const float* node = (const float*)d_in[0];
    const float* sub  = (const float*)d_in[1];
    const float* Wq   = (const float*)d_in[2];
    const float* bq   = (const float*)d_in[3];
    const float* Wk   = (const float*)d_in[4];
    const float* bk   = (const float*)d_in[5];
    const float* Wv   = (const float*)d_in[6];
    const float* bv   = (const float*)d_in[7];
    const float* in_w = (const float*)d_in[8];
    const float* in_b = (const float*)d_in[9];
    const float* out_w = (const float*)d_in[10];
    const float* out_b = (const float*)d_in[11];
    const float* fc_w  = (const float*)d_in[12];
    const float* fc_b  = (const float*)d_in[13];
    float* out = (float*)d_out;

    static int inited = 0;
    if (!inited) {
        cudaFuncSetAttribute(fused_qkv_attn, cudaFuncAttributeMaxDynamicSharedMemorySize, G1_SMEM);
        cudaFuncSetAttribute(out_gemm, cudaFuncAttributeMaxDynamicSharedMemorySize, G2_SMEM);
        inited = 1;
    }

    prep_kernel<<<896, 128>>>(Wq, bq, Wk, bk, Wv, bv, in_w, in_b, out_w, out_b, fc_w, fc_b);
    fused_qkv_attn<<<NGROUPS / 16, 512, G1_SMEM>>>(node, sub);
    out_gemm<<<NGROUPS / 64, 256, G2_SMEM>>>(out);
}

// round 7
// speedup vs baseline: 3.8577x; 1.1969x over previous
#include <cuda_runtime.h>
#include <cuda_fp16.h>
#include <cstdint>

// B=8, N=64, T=128, E=128, H=8, R=4, DH=16
#define NGROUPS 65536

// ---------------- device scratch ----------------
// fp16 B-fragment layouts for mma.sync.m16n8k16 (row.col)
__device__ __half g_Wqkv_frag[8 * 48 * 32 * 4];   // K=128 (8 kt), N=384 (48 nt): 96KB
__device__ float  g_bqkv[384];
__device__ __half g_Wof_frag[32 * 16 * 32 * 4];   // K=512 (32 kt), N=128 (16 nt): 128KB
__device__ float  g_bof[128];
__device__ __half g_ocat[(size_t)NGROUPS * 512];  // attention output (pre out_w), fp16

// ---------------- helpers ----------------
__device__ __forceinline__ void mma_f16(float c[4], const uint32_t a[4], const uint32_t b[2]) {
    asm volatile(
        "mma.sync.aligned.m16n8k16.row.col.f32.f16.f16.f32 "
        "{%0,%1,%2,%3}, {%4,%5,%6,%7}, {%8,%9}, {%0,%1,%2,%3};"
        : "+f"(c[0]), "+f"(c[1]), "+f"(c[2]), "+f"(c[3])
        : "r"(a[0]), "r"(a[1]), "r"(a[2]), "r"(a[3]), "r"(b[0]), "r"(b[1]));
}
__device__ __forceinline__ uint32_t smem_u32(const void* p) {
    uint32_t a;
    asm("{ .reg .u64 t; cvta.to.shared.u64 t, %1; cvt.u32.u64 %0, t; }" : "=r"(a) : "l"(p));
    return a;
}
__device__ __forceinline__ void cp_async16(uint32_t dst, const void* src) {
    asm volatile("cp.async.ca.shared.global [%0], [%1], 16;" :: "r"(dst), "l"(src));
}
__device__ __forceinline__ void cp_async_wait_all() {
    asm volatile("cp.async.commit_group;");
    asm volatile("cp.async.wait_group 0;");
}
__device__ __forceinline__ void ldmatrix_x4(uint32_t a[4], uint32_t addr) {
    asm volatile("ldmatrix.sync.aligned.m8n8.x4.shared.b16 {%0,%1,%2,%3}, [%4];"
                 : "=r"(a[0]), "=r"(a[1]), "=r"(a[2]), "=r"(a[3]) : "r"(addr));
}
__device__ __forceinline__ float warp_red(float v) {
    #pragma unroll
    for (int o = 16; o > 0; o >>= 1) v += __shfl_xor_sync(0xffffffffu, v, o);
    return v;
}

// ---------------- weight folding -> fp16 fragment layouts ----------------
__global__ void prep_kernel(const float* __restrict__ Wq, const float* __restrict__ bq,
                            const float* __restrict__ Wk, const float* __restrict__ bk,
                            const float* __restrict__ Wv, const float* __restrict__ bv,
                            const float* __restrict__ in_w, const float* __restrict__ in_b,
                            const float* __restrict__ out_w, const float* __restrict__ out_b,
                            const float* __restrict__ fc_w, const float* __restrict__ fc_b)
{
    int row = blockIdx.x;
    int t   = threadIdx.x;  // 0..127

    if (row < 384) {
        int n = row, sub = n >> 7;
        const float* W    = (sub == 0) ? Wq : (sub == 1) ? Wk : Wv;
        const float* bvec = (sub == 0) ? bq : (sub == 1) ? bk : bv;
        const float* iw   = in_w + (size_t)n * 128;
        float a0 = 0.f, a1 = 0.f, a2 = 0.f, a3 = 0.f;
        #pragma unroll 8
        for (int e = 0; e < 128; e += 4) {
            a0 = fmaf(iw[e + 0], W[(e + 0) * 128 + t], a0);
            a1 = fmaf(iw[e + 1], W[(e + 1) * 128 + t], a1);
            a2 = fmaf(iw[e + 2], W[(e + 2) * 128 + t], a2);
            a3 = fmaf(iw[e + 3], W[(e + 3) * 128 + t], a3);
        }
        float val = (a0 + a1) + (a2 + a3);
        int k = t;
        int kt = k >> 4, j = (k >> 3) & 1, hh = k & 1;
        int lane = ((n & 7) << 2) | ((k >> 1) & 3);
        int nt = n >> 3;
        g_Wqkv_frag[(((kt * 48 + nt) * 32 + lane) * 2 + j) * 2 + hh] = __float2half_rn(val);

        if (t < 32) {
            float p = 0.f;
            for (int e = t; e < 128; e += 32) p = fmaf(iw[e], bvec[e], p);
            p = warp_red(p);
            if (t == 0) g_bqkv[n] = p + in_b[n];
        }
    } else {
        int idx = row - 384;
        int r  = idx >> 7;
        int eo = idx & 127;
        const float* fw = fc_w + (size_t)eo * 512 + r * 128;
        float a0 = 0.f, a1 = 0.f, a2 = 0.f, a3 = 0.f;
        #pragma unroll 8
        for (int f = 0; f < 128; f += 4) {
            a0 = fmaf(fw[f + 0], out_w[(f + 0) * 128 + t], a0);
            a1 = fmaf(fw[f + 1], out_w[(f + 1) * 128 + t], a1);
            a2 = fmaf(fw[f + 2], out_w[(f + 2) * 128 + t], a2);
            a3 = fmaf(fw[f + 3], out_w[(f + 3) * 128 + t], a3);
        }
        float val = (a0 + a1) + (a2 + a3);
        int n = eo, k = r * 128 + t;
        int kt = k >> 4, j = (k >> 3) & 1, hh = k & 1;
        int lane = ((n & 7) << 2) | ((k >> 1) & 3);
        int nt = n >> 3;
        g_Wof_frag[(((kt * 16 + nt) * 32 + lane) * 2 + j) * 2 + hh] = __float2half_rn(val);

        if (r == 0 && t < 32) {
            const float* fwa = fc_w + (size_t)eo * 512;
            float p = 0.f;
            for (int c = t; c < 512; c += 32) p = fmaf(fwa[c], out_b[c & 127], p);
            p = warp_red(p);
            if (t == 0) g_bof[eo] = p + fc_b[eo];
        }
    }
}

// ---------------- fused: gather + fp16 QKV GEMM + attention -> g_ocat -------
// 512 threads (16 warps), 16 groups (64 rows), N=384, K=128.
// All weights resident in smem (96KB, one-shot cp.async).
// warp w: wmg=w&1 -> mtiles {2wmg, 2wmg+1}; wng=w>>1 -> ntiles wng*6..+5.
// smem: phase A: Xfrag u32[4mt][8kt][32][4] @0 (16KB), Wc 96KB @16384
//       phase B: qs f32[64][392] @0 (100352)
//       bias f32[384] @114688
#define QS_STRIDE 392
#define G1_SMEM (114688 + 1536)
__global__ void __launch_bounds__(512) fused_qkv_attn(const float* __restrict__ node,
                                                      const float* __restrict__ sub)
{
    extern __shared__ __align__(16) char smem[];
    uint32_t* Xf  = (uint32_t*)smem;            // 4096 u32
    uint32_t* Wc  = (uint32_t*)(smem + 16384);  // 24576 u32
    float*    qs  = (float*)smem;
    float*    bsm = (float*)(smem + 114688);

    int t    = threadIdx.x;
    int g0   = blockIdx.x * 16;
    int w    = t >> 5;
    int lane = t & 31;
    int wmg  = w & 1;
    int wng  = w >> 1;

    // one-shot async weight copy (6144 x 16B = 96KB)
    {
        uint32_t wdst = smem_u32(Wc);
        const uint4* src = (const uint4*)g_Wqkv_frag;
        #pragma unroll
        for (int i = 0; i < 12; i++) {
            int idx = t + i * 512;
            cp_async16(wdst + idx * 16, src + idx);
        }
    }
    for (int i = t; i < 384; i += 512) bsm[i] = g_bqkv[i];

    // gather X into fp16 A-fragment layout (overlaps cp.async)
    for (int idx = t; idx < 4096; idx += 512) {
        int j  = idx & 3;
        int ln = (idx >> 2) & 31;
        int kt = (idx >> 7) & 7;
        int mt = idx >> 10;
        int rowl = mt * 16 + (ln >> 2) + (j & 1) * 8;
        int k0   = kt * 16 + (ln & 3) * 2 + ((j >> 1) & 1) * 8;
        int g = g0 + (rowl >> 2), r = rowl & 3;
        float x0, x1;
        if (r == 0) {
            float2 v = *(const float2*)&node[(size_t)g * 128 + k0];
            x0 = v.x; x1 = v.y;
        } else {
            const float* s = &sub[(size_t)g * 384 + k0 * 3 + (r - 1)];
            x0 = s[0]; x1 = s[3];
        }
        __half2 hv = __floats2half2_rn(x0, x1);
        Xf[idx] = *(uint32_t*)&hv;
    }
    cp_async_wait_all();
    __syncthreads();

    float c[12][4];   // [mt_i*6 + n][4]
    #pragma unroll
    for (int n = 0; n < 12; n++)
        #pragma unroll
        for (int jj = 0; jj < 4; jj++) c[n][jj] = 0.f;

    // uninterrupted MMA mainloop: 8 kt x (2 mt x 6 nt)
    #pragma unroll
    for (int kt = 0; kt < 8; kt++) {
        uint32_t a[2][4];
        #pragma unroll
        for (int m = 0; m < 2; m++)
            *(uint4*)a[m] = *(const uint4*)&Xf[(((wmg * 2 + m) * 8 + kt) * 32 + lane) * 4];
        #pragma unroll
        for (int n = 0; n < 6; n++) {
            uint32_t b[2];
            *(uint2*)b = *(const uint2*)&Wc[((kt * 48 + wng * 6 + n) * 32 + lane) * 2];
            mma_f16(c[n], a[0], b);
            mma_f16(c[6 + n], a[1], b);
        }
    }
    __syncthreads();   // Xf/Wc reads done before qs overwrite

    // epilogue: +bias, store qkv to qs
    #pragma unroll
    for (int m = 0; m < 2; m++) {
        int row0 = (wmg * 2 + m) * 16 + (lane >> 2);
        #pragma unroll
        for (int n = 0; n < 6; n++) {
            int col = (wng * 6 + n) * 8 + (lane & 3) * 2;
            float2 bb = *(const float2*)&bsm[col];
            *(float2*)&qs[row0 * QS_STRIDE + col] =
                make_float2(c[m * 6 + n][0] + bb.x, c[m * 6 + n][1] + bb.y);
            *(float2*)&qs[(row0 + 8) * QS_STRIDE + col] =
                make_float2(c[m * 6 + n][2] + bb.x, c[m * 6 + n][3] + bb.y);
        }
    }
    __syncthreads();

    // attention: thread = (g, h, r)
    {
        int g = t >> 5;
        int h = (t >> 2) & 7;
        int r = t & 3;
        const float* rowbase = qs + (size_t)(g * 4) * QS_STRIDE + h * 16;

        float4 q[4];
        const float4* qp = (const float4*)(rowbase + r * QS_STRIDE);
        #pragma unroll
        for (int d = 0; d < 4; d++) q[d] = qp[d];

        float s[4];
        #pragma unroll
        for (int cc = 0; cc < 4; cc++) {
            const float4* kp = (const float4*)(rowbase + cc * QS_STRIDE + 128);
            float a = 0.f;
            #pragma unroll
            for (int d = 0; d < 4; d++) {
                float4 kv = kp[d];
                a = fmaf(q[d].x, kv.x, a);
                a = fmaf(q[d].y, kv.y, a);
                a = fmaf(q[d].z, kv.z, a);
                a = fmaf(q[d].w, kv.w, a);
            }
            s[cc] = a * 0.25f;
        }

        float m  = fmaxf(fmaxf(s[0], s[1]), fmaxf(s[2], s[3]));
        float e0 = __expf(s[0] - m), e1 = __expf(s[1] - m);
        float e2 = __expf(s[2] - m), e3 = __expf(s[3] - m);
        float inv = 1.f / (e0 + e1 + e2 + e3);
        float aw[4] = {e0 * inv, e1 * inv, e2 * inv, e3 * inv};

        float o[16];
        #pragma unroll
        for (int d = 0; d < 16; d++) o[d] = 0.f;
        #pragma unroll
        for (int cc = 0; cc < 4; cc++) {
            const float* vp = rowbase + cc * QS_STRIDE + 256;
            float a = aw[cc];
            #pragma unroll
            for (int d = 0; d < 16; d++) o[d] = fmaf(a, vp[d], o[d]);
        }

        __half2 oh[8];
        #pragma unroll
        for (int jj = 0; jj < 8; jj++) oh[jj] = __floats2half2_rn(o[2 * jj], o[2 * jj + 1]);
        __half* dst = &g_ocat[(size_t)(g0 + g) * 512 + r * 128 + h * 16];
        *(uint4*)dst       = *(uint4*)&oh[0];
        *(uint4*)(dst + 8) = *(uint4*)&oh[4];
    }
}

// ---------------- GEMM2: ocat[64,512](fp16) @ Wof -> out[64,128] ------------
// 512 threads (16 warps), 64 groups. All of Wof (128KB) + A (64KB) resident.
// warp w: wmg=w&1 -> mtiles {2wmg, 2wmg+1}; wng=w>>1 -> ntiles {2wng, 2wng+1}.
#define AS_STRIDE 520   // halves per row (512 + 8 pad)
#define G2_SMEM (131072 + 66560 + 512)
__global__ void __launch_bounds__(512) out_gemm(float* __restrict__ out)
{
    extern __shared__ __align__(16) char smem[];
    uint32_t* Wc  = (uint32_t*)smem;               // 32768 u32 (128KB)
    __half*   As  = (__half*)(smem + 131072);      // 64 x 520 halves
    float*    bsm = (float*)(smem + 131072 + 66560);

    int t    = threadIdx.x;
    int g0   = blockIdx.x * 64;
    int w    = t >> 5;
    int lane = t & 31;
    int wmg  = w & 1;
    int wng  = w >> 1;

    // one-shot async copies: B 8192x16B (128KB), A 4096x16B (64KB)
    {
        uint32_t wdst = smem_u32(Wc);
        const uint4* src = (const uint4*)g_Wof_frag;
        #pragma unroll
        for (int i = 0; i < 16; i++) {
            int idx = t + i * 512;
            cp_async16(wdst + idx * 16, src + idx);
        }
        uint32_t adst = smem_u32(As);
        #pragma unroll
        for (int i = 0; i < 8; i++) {
            int idx = t + i * 512;            // idx = row*64 + k8
            int row = idx >> 6, k8 = idx & 63;
            cp_async16(adst + (row * AS_STRIDE + k8 * 8) * 2,
                       &g_ocat[(size_t)(g0 + row) * 512 + k8 * 8]);
        }
    }
    if (t < 128) bsm[t] = g_bof[t];
    cp_async_wait_all();
    __syncthreads();

    float c[2][2][4];
    #pragma unroll
    for (int m = 0; m < 2; m++)
        #pragma unroll
        for (int n = 0; n < 2; n++)
            #pragma unroll
            for (int jj = 0; jj < 4; jj++) c[m][n][jj] = 0.f;

    uint32_t as_base = smem_u32(As);
    // ldmatrix address: row = mt*16 + (lane&15), kcol = ks*16 + (lane>>4)*8
    uint32_t arow_off = (uint32_t)(lane & 15) * (AS_STRIDE * 2) + (uint32_t)(lane >> 4) * 16;

    #pragma unroll 4
    for (int ks = 0; ks < 32; ks++) {
        uint32_t a[2][4];
        #pragma unroll
        for (int m = 0; m < 2; m++) {
            uint32_t addr = as_base + ((wmg * 2 + m) * 16) * (AS_STRIDE * 2)
                          + ks * 32 + arow_off;
            ldmatrix_x4(a[m], addr);
        }
        #pragma unroll
        for (int n = 0; n < 2; n++) {
            uint32_t b[2];
            *(uint2*)b = *(const uint2*)&Wc[((ks * 16 + wng * 2 + n) * 32 + lane) * 2];
            mma_f16(c[0][n], a[0], b);
            mma_f16(c[1][n], a[1], b);
        }
    }

    #pragma unroll
    for (int m = 0; m < 2; m++) {
        int row0 = g0 + (wmg * 2 + m) * 16 + (lane >> 2);
        #pragma unroll
        for (int n = 0; n < 2; n++) {
            int col = (wng * 2 + n) * 8 + (lane & 3) * 2;
            float2 bb = *(const float2*)&bsm[col];
            *(float2*)&out[(size_t)row0 * 128 + col] =
                make_float2(c[m][n][0] + bb.x, c[m][n][1] + bb.y);
            *(float2*)&out[(size_t)(row0 + 8) * 128 + col] =
                make_float2(c[m][n][2] + bb.x, c[m][n][3] + bb.y);
        }
    }
}

// ---------------- launch ----------------
extern "C" void kernel_launch(void* const* d_in, const int* in_sizes, int n_in,
                              void* d_out, int out_size)
{
    const float* node = (const float*)d_in[0];
    const float* sub  = (const float*)d_in[1];
    const float* Wq   = (const float*)d_in[2];
    const float* bq   = (const float*)d_in[3];
    const float* Wk   = (const float*)d_in[4];
    const float* bk   = (const float*)d_in[5];
    const float* Wv   = (const float*)d_in[6];
    const float* bv   = (const float*)d_in[7];
    const float* in_w = (const float*)d_in[8];
    const float* in_b = (const float*)d_in[9];
    const float* out_w = (const float*)d_in[10];
    const float* out_b = (const float*)d_in[11];
    const float* fc_w  = (const float*)d_in[12];
    const float* fc_b  = (const float*)d_in[13];
    float* out = (float*)d_out;

    static int inited = 0;
    if (!inited) {
        cudaFuncSetAttribute(fused_qkv_attn, cudaFuncAttributeMaxDynamicSharedMemorySize, G1_SMEM);
        cudaFuncSetAttribute(out_gemm, cudaFuncAttributeMaxDynamicSharedMemorySize, G2_SMEM);
        inited = 1;
    }

    prep_kernel<<<896, 128>>>(Wq, bq, Wk, bk, Wv, bv, in_w, in_b, out_w, out_b, fc_w, fc_b);
    fused_qkv_attn<<<NGROUPS / 16, 512, G1_SMEM>>>(node, sub);
    out_gemm<<<NGROUPS / 64, 512, G2_SMEM>>>(out);
}